// round 13
// baseline (speedup 1.0000x reference)
#include <cuda_runtime.h>
#include <cuda_fp16.h>
#include <cstdint>

#define BATCH 2
#define SEQ   2048
#define HDIM  1024
#define NHEAD 16
#define HD    64
#define MROWS (BATCH * SEQ)   // 4096

// ---------------- scratch (device globals: allocation-free) ------------------
__device__ __half g_Qh[MROWS * HDIM];
__device__ __half g_Kh[MROWS * HDIM];
__device__ __half g_Vh[MROWS * HDIM];
__device__ __half g_AOh[MROWS * HDIM];
__device__ __half g_Yh[MROWS * HDIM];
__device__ __half g_qx[MROWS * HDIM];
__device__ __half g_kx[MROWS * HDIM];
__device__ __half g_vx[MROWS * HDIM];
__device__ __half g_Wqh[HDIM * HDIM];
__device__ __half g_Wkh[HDIM * HDIM];
__device__ __half g_Wvh[HDIM * HDIM];
__device__ __half g_Woh[HDIM * HDIM];

// ---------------- helpers ----------------------------------------------------
__device__ __forceinline__ void mma16816h(float* c, const uint32_t* a, const uint32_t* b) {
    asm volatile(
        "mma.sync.aligned.m16n8k16.row.col.f32.f16.f16.f32 "
        "{%0,%1,%2,%3},{%4,%5,%6,%7},{%8,%9},{%0,%1,%2,%3};"
        : "+f"(c[0]), "+f"(c[1]), "+f"(c[2]), "+f"(c[3])
        : "r"(a[0]), "r"(a[1]), "r"(a[2]), "r"(a[3]), "r"(b[0]), "r"(b[1]));
}

__device__ __forceinline__ void ldsm_x4(uint32_t& r0, uint32_t& r1, uint32_t& r2,
                                        uint32_t& r3, uint32_t addr) {
    asm volatile("ldmatrix.sync.aligned.m8n8.x4.shared.b16 {%0,%1,%2,%3}, [%4];"
                 : "=r"(r0), "=r"(r1), "=r"(r2), "=r"(r3) : "r"(addr));
}
__device__ __forceinline__ void ldsm_x4t(uint32_t& r0, uint32_t& r1, uint32_t& r2,
                                         uint32_t& r3, uint32_t addr) {
    asm volatile("ldmatrix.sync.aligned.m8n8.x4.trans.shared.b16 {%0,%1,%2,%3}, [%4];"
                 : "=r"(r0), "=r"(r1), "=r"(r2), "=r"(r3) : "r"(addr));
}

__device__ __forceinline__ void cp16(uint32_t dst, const void* src) {
    asm volatile("cp.async.cg.shared.global [%0], [%1], 16;" :: "r"(dst), "l"(src));
}
__device__ __forceinline__ void cp_commit() {
    asm volatile("cp.async.commit_group;");
}
template <int N>
__device__ __forceinline__ void cp_wait() {
    asm volatile("cp.async.wait_group %0;" :: "n"(N));
}

// ---------------- fp32 -> fp16 batched convert --------------------------------
__global__ void __launch_bounds__(256) cvt7(
    const float* s0, const float* s1, const float* s2, const float* s3,
    const float* s4, const float* s5, const float* s6,
    __half* d0, __half* d1, __half* d2, __half* d3,
    __half* d4, __half* d5, __half* d6,
    int nbig, int nsmall)
{
    const float* s;
    __half* d;
    int n;
    switch (blockIdx.y) {
        case 0: s = s0; d = d0; n = nbig; break;
        case 1: s = s1; d = d1; n = nbig; break;
        case 2: s = s2; d = d2; n = nbig; break;
        case 3: s = s3; d = d3; n = nsmall; break;
        case 4: s = s4; d = d4; n = nsmall; break;
        case 5: s = s5; d = d5; n = nsmall; break;
        default: s = s6; d = d6; n = nsmall; break;
    }
    int idx = (blockIdx.x * 256 + threadIdx.x) * 4;
    if (idx < n) {
        float4 v = *(const float4*)(s + idx);
        *(__half2*)(d + idx)     = __floats2half2_rn(v.x, v.y);
        *(__half2*)(d + idx + 2) = __floats2half2_rn(v.z, v.w);
    }
}

// ---------------- fp16 GEMM: C = A[M,K] @ W[N,K]^T + bias (fp16 out) ---------
// 256x128 CTA tile, BK=32, 3-stage cp.async ring, 16 warps (4x4), warp 64x32.
#define GHS 40
#define A_ST (256 * GHS)
#define B_ST (128 * GHS)
#define PAIR_ST (A_ST + B_ST)
#define G_SMEM_BYTES (3 * PAIR_ST * 2)

__device__ __forceinline__ void gemm_core(
    const __half* __restrict__ A, const __half* __restrict__ W,
    const float* __restrict__ bias, __half* __restrict__ C,
    int M, int N, int K, __half* smem, int m0, int n0)
{
    const int tid  = threadIdx.x;
    const int w    = tid >> 5;
    const int lane = tid & 31;
    const int g    = lane >> 2;
    const int t    = lane & 3;
    const int wm   = (w >> 2) * 64;
    const int wn   = (w & 3) * 32;

    const uint32_t s_base = (uint32_t)__cvta_generic_to_shared(smem);

    const int a_row  = lane & 15;
    const int a_chi  = (lane >> 4) * 8;
    const int kn_row = (lane & 7) + ((lane >> 4) & 1) * 8;
    const int kn_col = ((lane >> 3) & 1) * 8;

    float acc[4][4][4];
    #pragma unroll
    for (int i = 0; i < 4; i++)
        #pragma unroll
        for (int j = 0; j < 4; j++)
            #pragma unroll
            for (int r = 0; r < 4; r++) acc[i][j][r] = 0.f;

    const int niter = K / 32;

    auto load_stage = [&](int stage, int kb) {
        const uint32_t sa = s_base + (uint32_t)stage * (PAIR_ST * 2);
        const uint32_t sb = sa + A_ST * 2;
        #pragma unroll
        for (int j = 0; j < 3; j++) {
            int cid = tid + j * 512;
            if (cid < 1024) {
                int r  = cid >> 2;
                int ch = (cid & 3) * 8;
                cp16(sa + (r * GHS + ch) * 2,
                     A + (size_t)(m0 + r) * K + kb * 32 + ch);
            } else {
                int c2 = cid - 1024;
                int r  = c2 >> 2;
                int ch = (c2 & 3) * 8;
                cp16(sb + (r * GHS + ch) * 2,
                     W + (size_t)(n0 + r) * K + kb * 32 + ch);
            }
        }
    };

    load_stage(0, 0); cp_commit();
    load_stage(1, 1); cp_commit();

    for (int kb = 0; kb < niter; kb++) {
        cp_wait<1>();
        __syncthreads();

        if (kb + 2 < niter) load_stage((kb + 2) % 3, kb + 2);
        cp_commit();

        const int cs = kb % 3;
        const uint32_t sa = s_base + (uint32_t)cs * (PAIR_ST * 2);
        const uint32_t sb = sa + A_ST * 2;

        #pragma unroll
        for (int ks = 0; ks < 2; ks++) {
            const int k0 = ks * 16;
            uint32_t af[4][4];
            #pragma unroll
            for (int mt = 0; mt < 4; mt++) {
                uint32_t addr = sa + ((wm + mt * 16 + a_row) * GHS + k0 + a_chi) * 2;
                ldsm_x4(af[mt][0], af[mt][1], af[mt][2], af[mt][3], addr);
            }
            uint32_t bfr[2][4];
            #pragma unroll
            for (int ng = 0; ng < 2; ng++) {
                uint32_t addr = sb + ((wn + ng * 16 + kn_row) * GHS + k0 + kn_col) * 2;
                ldsm_x4(bfr[ng][0], bfr[ng][1], bfr[ng][2], bfr[ng][3], addr);
            }
            #pragma unroll
            for (int mt = 0; mt < 4; mt++)
                #pragma unroll
                for (int nt = 0; nt < 4; nt++) {
                    uint32_t bf[2] = {bfr[nt >> 1][(nt & 1) * 2],
                                      bfr[nt >> 1][(nt & 1) * 2 + 1]};
                    mma16816h(acc[mt][nt], af[mt], bf);
                }
        }
    }

    #pragma unroll
    for (int mt = 0; mt < 4; mt++) {
        const int row0 = m0 + wm + mt * 16 + g;
        const int row1 = row0 + 8;
        #pragma unroll
        for (int nt = 0; nt < 4; nt++) {
            const int col = n0 + wn + nt * 8 + t * 2;
            const float b0 = bias[col], b1 = bias[col + 1];
            *(__half2*)(C + (size_t)row0 * N + col) =
                __floats2half2_rn(acc[mt][nt][0] + b0, acc[mt][nt][1] + b1);
            *(__half2*)(C + (size_t)row1 * N + col) =
                __floats2half2_rn(acc[mt][nt][2] + b0, acc[mt][nt][3] + b1);
        }
    }
}

__global__ void __launch_bounds__(512, 1) gemm_qkv(
    const __half* Aq, const __half* Ak, const __half* Av,
    const __half* Wq, const __half* Wk, const __half* Wv,
    const float* bq, const float* bk, const float* bv,
    __half* Cq, __half* Ck, __half* Cv)
{
    extern __shared__ __half gsm[];
    const int z = blockIdx.z;
    const __half* A = (z == 0) ? Aq : (z == 1) ? Ak : Av;
    const __half* W = (z == 0) ? Wq : (z == 1) ? Wk : Wv;
    const float*  b = (z == 0) ? bq : (z == 1) ? bk : bv;
    __half*       C = (z == 0) ? Cq : (z == 1) ? Ck : Cv;
    gemm_core(A, W, b, C, MROWS, HDIM, HDIM, gsm,
              blockIdx.y * 256, blockIdx.x * 128);
}

__global__ void __launch_bounds__(512, 1) gemm_o(
    const __half* A, const __half* W, const float* bias, __half* C)
{
    extern __shared__ __half gsm[];
    gemm_core(A, W, bias, C, MROWS, HDIM, HDIM, gsm,
              blockIdx.y * 256, blockIdx.x * 128);
}

// ---------------- FA2-style fp16 flash attention (causal) --------------------
// 256 q-rows/block (16 warps x 16 rows), K-tile 64, 3-stage cp.async pipeline.
#define KS_STR 72
#define A_STAGE (64 * KS_STR)
#define A_SMEM_HALVES (3 * 2 * A_STAGE)   // 27648 halves = 55296 B

__global__ void __launch_bounds__(512, 1) attn_fa(
    const __half* __restrict__ Qh, const __half* __restrict__ Kh,
    const __half* __restrict__ Vh, __half* __restrict__ O)
{
    extern __shared__ __half asm_[];
    __half* Ks = asm_;
    __half* Vs = asm_ + 3 * A_STAGE;

    const int tid  = threadIdx.x;
    const int w    = tid >> 5;          // 0..15
    const int lane = tid & 31;
    const int g    = lane >> 2;
    const int t    = lane & 3;
    const int wq   = w * 16;            // 0..240

    const int q0 = (gridDim.x - 1 - blockIdx.x) * 256;
    const int h  = blockIdx.y;
    const int b  = blockIdx.z;

    const uint32_t ks_base = (uint32_t)__cvta_generic_to_shared(Ks);
    const uint32_t vs_base = (uint32_t)__cvta_generic_to_shared(Vs);
    const uint32_t stage_b = A_STAGE * 2;

    // ---- stage Q tile [256][64] linearly across the whole 6-stage region ----
    const __half* Qg = Qh + ((size_t)(b * SEQ + q0)) * HDIM + h * HD;
    #pragma unroll
    for (int j = 0; j < 4; j++) {
        int i = tid + j * 512;          // 0..2047 chunks of 8 halves
        int r = i >> 3;                 // 0..255
        int c8 = (i & 7) * 8;
        cp16(ks_base + (r * KS_STR + c8) * 2, Qg + (size_t)r * HDIM + c8);
    }
    cp_commit();
    cp_wait<0>();
    __syncthreads();

    uint32_t qf[4][4];
    {
        const __half2 sc = __half2half2(__float2half(0.125f * 1.44269504f));
        const int row = wq + (lane & 15);
        const int chi = (lane >> 4) * 8;
        #pragma unroll
        for (int ks = 0; ks < 4; ks++) {
            uint32_t addr = ks_base + (row * KS_STR + ks * 16 + chi) * 2;
            ldsm_x4(qf[ks][0], qf[ks][1], qf[ks][2], qf[ks][3], addr);
            #pragma unroll
            for (int r = 0; r < 4; r++) {
                __half2 v = *(__half2*)&qf[ks][r];
                v = __hmul2(v, sc);
                qf[ks][r] = *(uint32_t*)&v;
            }
        }
    }
    __syncthreads();

    float m0r = -1e30f, m1r = -1e30f, l0r = 0.f, l1r = 0.f;
    float oacc[8][4];
    #pragma unroll
    for (int j = 0; j < 8; j++)
        #pragma unroll
        for (int r = 0; r < 4; r++) oacc[j][r] = 0.f;

    const int kn_row = (lane & 7) + ((lane >> 4) & 1) * 8;
    const int kn_col = ((lane >> 3) & 1) * 8;
    const int vk_row = (lane & 7) + ((lane >> 3) & 1) * 8;
    const int vn_col = (lane >> 4) * 8;

    const int jmax = (q0 + 255) / 64;

    // prologue: tiles 0,1 (512 K-chunks + 512 V-chunks each; 1 K + 1 V per thread)
    #pragma unroll
    for (int p = 0; p < 2; p++) {
        if (p <= jmax) {
            const uint32_t st = p * stage_b;
            const __half* Kg = Kh + ((size_t)(b * SEQ + p * 64)) * HDIM + h * HD;
            const __half* Vg = Vh + ((size_t)(b * SEQ + p * 64)) * HDIM + h * HD;
            int r = tid >> 3;
            int c8 = (tid & 7) * 8;
            cp16(ks_base + st + (r * KS_STR + c8) * 2, Kg + (size_t)r * HDIM + c8);
            cp16(vs_base + st + (r * KS_STR + c8) * 2, Vg + (size_t)r * HDIM + c8);
        }
        cp_commit();
    }

    for (int jt = 0; jt <= jmax; jt++) {
        const int k0g = jt * 64;

        cp_wait<1>();
        __syncthreads();

        if (jt + 2 <= jmax) {
            const int s = (jt + 2) % 3;
            const uint32_t st = s * stage_b;
            const __half* Kg = Kh + ((size_t)(b * SEQ + (jt + 2) * 64)) * HDIM + h * HD;
            const __half* Vg = Vh + ((size_t)(b * SEQ + (jt + 2) * 64)) * HDIM + h * HD;
            int r = tid >> 3;
            int c8 = (tid & 7) * 8;
            cp16(ks_base + st + (r * KS_STR + c8) * 2, Kg + (size_t)r * HDIM + c8);
            cp16(vs_base + st + (r * KS_STR + c8) * 2, Vg + (size_t)r * HDIM + c8);
        }
        cp_commit();

        const uint32_t sk = ks_base + (jt % 3) * stage_b;
        const uint32_t sv = vs_base + (jt % 3) * stage_b;

        const bool active = (k0g <= q0 + wq + 15);
        if (active) {
            float sacc[8][4];
            #pragma unroll
            for (int j = 0; j < 8; j++)
                #pragma unroll
                for (int r = 0; r < 4; r++) sacc[j][r] = 0.f;

            #pragma unroll
            for (int ks = 0; ks < 4; ks++) {
                #pragma unroll
                for (int ng = 0; ng < 4; ng++) {
                    uint32_t b0, b1, b2, b3;
                    uint32_t addr = sk + ((ng * 16 + kn_row) * KS_STR + ks * 16 + kn_col) * 2;
                    ldsm_x4(b0, b1, b2, b3, addr);
                    uint32_t bf0[2] = {b0, b1}, bf1[2] = {b2, b3};
                    mma16816h(sacc[ng * 2],     qf[ks], bf0);
                    mma16816h(sacc[ng * 2 + 1], qf[ks], bf1);
                }
            }

            if (k0g + 63 > q0 + wq) {
                const int row0 = q0 + wq + g;
                const int row1 = row0 + 8;
                #pragma unroll
                for (int j = 0; j < 8; j++) {
                    const int col = k0g + j * 8 + t * 2;
                    if (col > row0)     sacc[j][0] = -1e30f;
                    if (col + 1 > row0) sacc[j][1] = -1e30f;
                    if (col > row1)     sacc[j][2] = -1e30f;
                    if (col + 1 > row1) sacc[j][3] = -1e30f;
                }
            }

            float tm0 = -1e30f, tm1 = -1e30f;
            #pragma unroll
            for (int j = 0; j < 8; j++) {
                tm0 = fmaxf(tm0, fmaxf(sacc[j][0], sacc[j][1]));
                tm1 = fmaxf(tm1, fmaxf(sacc[j][2], sacc[j][3]));
            }
            tm0 = fmaxf(tm0, __shfl_xor_sync(0xffffffffu, tm0, 1));
            tm0 = fmaxf(tm0, __shfl_xor_sync(0xffffffffu, tm0, 2));
            tm1 = fmaxf(tm1, __shfl_xor_sync(0xffffffffu, tm1, 1));
            tm1 = fmaxf(tm1, __shfl_xor_sync(0xffffffffu, tm1, 2));

            const float mn0 = fmaxf(m0r, tm0);
            const float mn1 = fmaxf(m1r, tm1);
            const float al0 = exp2f(m0r - mn0);
            const float al1 = exp2f(m1r - mn1);
            m0r = mn0; m1r = mn1;

            float rs0 = 0.f, rs1 = 0.f;
            #pragma unroll
            for (int j = 0; j < 8; j++) {
                sacc[j][0] = exp2f(sacc[j][0] - mn0);
                sacc[j][1] = exp2f(sacc[j][1] - mn0);
                sacc[j][2] = exp2f(sacc[j][2] - mn1);
                sacc[j][3] = exp2f(sacc[j][3] - mn1);
                rs0 += sacc[j][0] + sacc[j][1];
                rs1 += sacc[j][2] + sacc[j][3];
            }
            rs0 += __shfl_xor_sync(0xffffffffu, rs0, 1);
            rs0 += __shfl_xor_sync(0xffffffffu, rs0, 2);
            rs1 += __shfl_xor_sync(0xffffffffu, rs1, 1);
            rs1 += __shfl_xor_sync(0xffffffffu, rs1, 2);
            l0r = l0r * al0 + rs0;
            l1r = l1r * al1 + rs1;

            uint32_t pa[4][4];
            #pragma unroll
            for (int ks = 0; ks < 4; ks++) {
                __half2 h0 = __floats2half2_rn(sacc[2*ks][0],   sacc[2*ks][1]);
                __half2 h1 = __floats2half2_rn(sacc[2*ks][2],   sacc[2*ks][3]);
                __half2 h2 = __floats2half2_rn(sacc[2*ks+1][0], sacc[2*ks+1][1]);
                __half2 h3 = __floats2half2_rn(sacc[2*ks+1][2], sacc[2*ks+1][3]);
                pa[ks][0] = *(uint32_t*)&h0; pa[ks][1] = *(uint32_t*)&h1;
                pa[ks][2] = *(uint32_t*)&h2; pa[ks][3] = *(uint32_t*)&h3;
            }

            #pragma unroll
            for (int j = 0; j < 8; j++) {
                oacc[j][0] *= al0; oacc[j][1] *= al0;
                oacc[j][2] *= al1; oacc[j][3] *= al1;
            }
            #pragma unroll
            for (int ks = 0; ks < 4; ks++) {
                #pragma unroll
                for (int ng = 0; ng < 4; ng++) {
                    uint32_t b0, b1, b2, b3;
                    uint32_t addr = sv + ((ks * 16 + vk_row) * KS_STR + ng * 16 + vn_col) * 2;
                    ldsm_x4t(b0, b1, b2, b3, addr);
                    uint32_t bf0[2] = {b0, b1}, bf1[2] = {b2, b3};
                    mma16816h(oacc[ng * 2],     pa[ks], bf0);
                    mma16816h(oacc[ng * 2 + 1], pa[ks], bf1);
                }
            }
        }
    }

    const float il0 = 1.f / l0r;
    const float il1 = 1.f / l1r;
    __half* Og = O + ((size_t)(b * SEQ + q0 + wq)) * HDIM + h * HD;
    #pragma unroll
    for (int j = 0; j < 8; j++) {
        const int col = j * 8 + t * 2;
        *(__half2*)(Og + (size_t)g * HDIM + col) =
            __floats2half2_rn(oacc[j][0] * il0, oacc[j][1] * il0);
        *(__half2*)(Og + (size_t)(g + 8) * HDIM + col) =
            __floats2half2_rn(oacc[j][2] * il1, oacc[j][3] * il1);
    }
}

// ---------------- Residual + LayerNorm (Y in fp16) ---------------------------
__global__ void __launch_bounds__(256) ln_kernel(
    const float* __restrict__ X, const __half* __restrict__ Y,
    const float* __restrict__ g, const float* __restrict__ be,
    float* __restrict__ out)
{
    const int row = blockIdx.x;
    const int tid = threadIdx.x;
    const float* xr = X + (size_t)row * HDIM;
    const __half* yr = Y + (size_t)row * HDIM;

    float4 x4 = *(const float4*)(xr + tid * 4);
    __half2 yh0 = *(const __half2*)(yr + tid * 4);
    __half2 yh1 = *(const __half2*)(yr + tid * 4 + 2);
    float2 y0 = __half22float2(yh0);
    float2 y1 = __half22float2(yh1);
    float v0 = x4.x + y0.x, v1 = x4.y + y0.y, v2 = x4.z + y1.x, v3 = x4.w + y1.y;

    float s  = v0 + v1 + v2 + v3;
    float ss = v0 * v0 + v1 * v1 + v2 * v2 + v3 * v3;
    #pragma unroll
    for (int off = 16; off > 0; off >>= 1) {
        s  += __shfl_xor_sync(0xffffffffu, s, off);
        ss += __shfl_xor_sync(0xffffffffu, ss, off);
    }

    __shared__ float sbuf[8], ssbuf[8];
    __shared__ float mu_s, rstd_s;
    if ((tid & 31) == 0) { sbuf[tid >> 5] = s; ssbuf[tid >> 5] = ss; }
    __syncthreads();
    if (tid == 0) {
        float S = 0.f, SS = 0.f;
        #pragma unroll
        for (int k = 0; k < 8; k++) { S += sbuf[k]; SS += ssbuf[k]; }
        float mu = S * (1.0f / HDIM);
        float var = SS * (1.0f / HDIM) - mu * mu;
        mu_s = mu;
        rstd_s = rsqrtf(var + 1e-5f);
    }
    __syncthreads();
    float mu = mu_s, rs = rstd_s;

    float4 g4 = *(const float4*)(g + tid * 4);
    float4 b4 = *(const float4*)(be + tid * 4);
    float4 o;
    o.x = (v0 - mu) * rs * g4.x + b4.x;
    o.y = (v1 - mu) * rs * g4.y + b4.y;
    o.z = (v2 - mu) * rs * g4.z + b4.z;
    o.w = (v3 - mu) * rs * g4.w + b4.w;
    *(float4*)(out + (size_t)row * HDIM + tid * 4) = o;
}

// ---------------- launch -----------------------------------------------------
extern "C" void kernel_launch(void* const* d_in, const int* in_sizes, int n_in,
                              void* d_out, int out_size)
{
    const float* query = (const float*)d_in[0];
    const float* key   = (const float*)d_in[1];
    const float* value = (const float*)d_in[2];
    const float* Wq = (const float*)d_in[4];
    const float* bq = (const float*)d_in[5];
    const float* Wk = (const float*)d_in[6];
    const float* bk = (const float*)d_in[7];
    const float* Wv = (const float*)d_in[8];
    const float* bv = (const float*)d_in[9];
    const float* Wo = (const float*)d_in[10];
    const float* bo = (const float*)d_in[11];
    const float* lg = (const float*)d_in[12];
    const float* lb = (const float*)d_in[13];
    float* out = (float*)d_out;

    __half *dQh, *dKh, *dVh, *dAOh, *dYh, *dqx, *dkx, *dvx, *dWq, *dWk, *dWv, *dWo;
    cudaGetSymbolAddress((void**)&dQh, g_Qh);
    cudaGetSymbolAddress((void**)&dKh, g_Kh);
    cudaGetSymbolAddress((void**)&dVh, g_Vh);
    cudaGetSymbolAddress((void**)&dAOh, g_AOh);
    cudaGetSymbolAddress((void**)&dYh, g_Yh);
    cudaGetSymbolAddress((void**)&dqx, g_qx);
    cudaGetSymbolAddress((void**)&dkx, g_kx);
    cudaGetSymbolAddress((void**)&dvx, g_vx);
    cudaGetSymbolAddress((void**)&dWq, g_Wqh);
    cudaGetSymbolAddress((void**)&dWk, g_Wkh);
    cudaGetSymbolAddress((void**)&dWv, g_Wvh);
    cudaGetSymbolAddress((void**)&dWo, g_Woh);

    const int nbig = MROWS * HDIM;
    const int nsmall = HDIM * HDIM;
    dim3 gCvt(nbig / (256 * 4), 7);
    cvt7<<<gCvt, 256>>>(query, key, value, Wq, Wk, Wv, Wo,
                        dqx, dkx, dvx, dWq, dWk, dWv, dWo, nbig, nsmall);

    cudaFuncSetAttribute(gemm_qkv, cudaFuncAttributeMaxDynamicSharedMemorySize, G_SMEM_BYTES);
    cudaFuncSetAttribute(gemm_o,   cudaFuncAttributeMaxDynamicSharedMemorySize, G_SMEM_BYTES);
    const int attn_smem = A_SMEM_HALVES * 2;
    cudaFuncSetAttribute(attn_fa, cudaFuncAttributeMaxDynamicSharedMemorySize, attn_smem);

    dim3 gQKV(HDIM / 128, MROWS / 256, 3);           // (8, 16, 3)
    gemm_qkv<<<gQKV, 512, G_SMEM_BYTES>>>(dqx, dkx, dvx, dWq, dWk, dWv,
                                          bq, bk, bv, dQh, dKh, dVh);

    attn_fa<<<dim3(SEQ / 256, NHEAD, BATCH), 512, attn_smem>>>(dQh, dKh, dVh, dAOh);

    dim3 gO(HDIM / 128, MROWS / 256);                // (8, 16)
    gemm_o<<<gO, 512, G_SMEM_BYTES>>>(dAOh, dWo, bo, dYh);

    ln_kernel<<<MROWS, 256>>>(query, dYh, lg, lb, out);
}

// round 14
// speedup vs baseline: 1.0372x; 1.0372x over previous
#include <cuda_runtime.h>
#include <cuda_fp16.h>
#include <cstdint>

#define BATCH 2
#define SEQ   2048
#define HDIM  1024
#define NHEAD 16
#define HD    64
#define MROWS (BATCH * SEQ)   // 4096

// ---------------- scratch (device globals: allocation-free) ------------------
__device__ __half g_Qh[MROWS * HDIM];
__device__ __half g_Kh[MROWS * HDIM];
__device__ __half g_Vh[MROWS * HDIM];
__device__ __half g_AOh[MROWS * HDIM];
__device__ __half g_Yh[MROWS * HDIM];
__device__ __half g_qx[MROWS * HDIM];
__device__ __half g_kx[MROWS * HDIM];
__device__ __half g_vx[MROWS * HDIM];
__device__ __half g_Wqh[HDIM * HDIM];
__device__ __half g_Wkh[HDIM * HDIM];
__device__ __half g_Wvh[HDIM * HDIM];
__device__ __half g_Woh[HDIM * HDIM];

// ---------------- helpers ----------------------------------------------------
__device__ __forceinline__ void mma16816h(float* c, const uint32_t* a, const uint32_t* b) {
    asm volatile(
        "mma.sync.aligned.m16n8k16.row.col.f32.f16.f16.f32 "
        "{%0,%1,%2,%3},{%4,%5,%6,%7},{%8,%9},{%0,%1,%2,%3};"
        : "+f"(c[0]), "+f"(c[1]), "+f"(c[2]), "+f"(c[3])
        : "r"(a[0]), "r"(a[1]), "r"(a[2]), "r"(a[3]), "r"(b[0]), "r"(b[1]));
}

__device__ __forceinline__ void ldsm_x4(uint32_t& r0, uint32_t& r1, uint32_t& r2,
                                        uint32_t& r3, uint32_t addr) {
    asm volatile("ldmatrix.sync.aligned.m8n8.x4.shared.b16 {%0,%1,%2,%3}, [%4];"
                 : "=r"(r0), "=r"(r1), "=r"(r2), "=r"(r3) : "r"(addr));
}
__device__ __forceinline__ void ldsm_x4t(uint32_t& r0, uint32_t& r1, uint32_t& r2,
                                         uint32_t& r3, uint32_t addr) {
    asm volatile("ldmatrix.sync.aligned.m8n8.x4.trans.shared.b16 {%0,%1,%2,%3}, [%4];"
                 : "=r"(r0), "=r"(r1), "=r"(r2), "=r"(r3) : "r"(addr));
}

__device__ __forceinline__ void cp16(uint32_t dst, const void* src) {
    asm volatile("cp.async.cg.shared.global [%0], [%1], 16;" :: "r"(dst), "l"(src));
}
__device__ __forceinline__ void cp_commit() {
    asm volatile("cp.async.commit_group;");
}
template <int N>
__device__ __forceinline__ void cp_wait() {
    asm volatile("cp.async.wait_group %0;" :: "n"(N));
}

// ---------------- fp32 -> fp16 batched convert --------------------------------
__global__ void __launch_bounds__(256) cvt7(
    const float* s0, const float* s1, const float* s2, const float* s3,
    const float* s4, const float* s5, const float* s6,
    __half* d0, __half* d1, __half* d2, __half* d3,
    __half* d4, __half* d5, __half* d6,
    int nbig, int nsmall)
{
    const float* s;
    __half* d;
    int n;
    switch (blockIdx.y) {
        case 0: s = s0; d = d0; n = nbig; break;
        case 1: s = s1; d = d1; n = nbig; break;
        case 2: s = s2; d = d2; n = nbig; break;
        case 3: s = s3; d = d3; n = nsmall; break;
        case 4: s = s4; d = d4; n = nsmall; break;
        case 5: s = s5; d = d5; n = nsmall; break;
        default: s = s6; d = d6; n = nsmall; break;
    }
    int idx = (blockIdx.x * 256 + threadIdx.x) * 4;
    if (idx < n) {
        float4 v = *(const float4*)(s + idx);
        *(__half2*)(d + idx)     = __floats2half2_rn(v.x, v.y);
        *(__half2*)(d + idx + 2) = __floats2half2_rn(v.z, v.w);
    }
}

// ---------------- fp16 GEMM: C = A[M,K] @ W[N,K]^T + bias (fp16 out) ---------
// 256x128 CTA tile, BK=32, 3-stage cp.async ring, 16 warps (4x4), warp 64x32.
#define GHS 40
#define A_ST (256 * GHS)
#define B_ST (128 * GHS)
#define PAIR_ST (A_ST + B_ST)
#define G_SMEM_BYTES (3 * PAIR_ST * 2)

__device__ __forceinline__ void gemm_core(
    const __half* __restrict__ A, const __half* __restrict__ W,
    const float* __restrict__ bias, __half* __restrict__ C,
    int M, int N, int K, __half* smem, int m0, int n0)
{
    const int tid  = threadIdx.x;
    const int w    = tid >> 5;
    const int lane = tid & 31;
    const int g    = lane >> 2;
    const int t    = lane & 3;
    const int wm   = (w >> 2) * 64;
    const int wn   = (w & 3) * 32;

    const uint32_t s_base = (uint32_t)__cvta_generic_to_shared(smem);

    const int a_row  = lane & 15;
    const int a_chi  = (lane >> 4) * 8;
    const int kn_row = (lane & 7) + ((lane >> 4) & 1) * 8;
    const int kn_col = ((lane >> 3) & 1) * 8;

    float acc[4][4][4];
    #pragma unroll
    for (int i = 0; i < 4; i++)
        #pragma unroll
        for (int j = 0; j < 4; j++)
            #pragma unroll
            for (int r = 0; r < 4; r++) acc[i][j][r] = 0.f;

    const int niter = K / 32;

    auto load_stage = [&](int stage, int kb) {
        const uint32_t sa = s_base + (uint32_t)stage * (PAIR_ST * 2);
        const uint32_t sb = sa + A_ST * 2;
        #pragma unroll
        for (int j = 0; j < 3; j++) {
            int cid = tid + j * 512;
            if (cid < 1024) {
                int r  = cid >> 2;
                int ch = (cid & 3) * 8;
                cp16(sa + (r * GHS + ch) * 2,
                     A + (size_t)(m0 + r) * K + kb * 32 + ch);
            } else {
                int c2 = cid - 1024;
                int r  = c2 >> 2;
                int ch = (c2 & 3) * 8;
                cp16(sb + (r * GHS + ch) * 2,
                     W + (size_t)(n0 + r) * K + kb * 32 + ch);
            }
        }
    };

    load_stage(0, 0); cp_commit();
    load_stage(1, 1); cp_commit();

    for (int kb = 0; kb < niter; kb++) {
        cp_wait<1>();
        __syncthreads();

        if (kb + 2 < niter) load_stage((kb + 2) % 3, kb + 2);
        cp_commit();

        const int cs = kb % 3;
        const uint32_t sa = s_base + (uint32_t)cs * (PAIR_ST * 2);
        const uint32_t sb = sa + A_ST * 2;

        #pragma unroll
        for (int ks = 0; ks < 2; ks++) {
            const int k0 = ks * 16;
            uint32_t af[4][4];
            #pragma unroll
            for (int mt = 0; mt < 4; mt++) {
                uint32_t addr = sa + ((wm + mt * 16 + a_row) * GHS + k0 + a_chi) * 2;
                ldsm_x4(af[mt][0], af[mt][1], af[mt][2], af[mt][3], addr);
            }
            uint32_t bfr[2][4];
            #pragma unroll
            for (int ng = 0; ng < 2; ng++) {
                uint32_t addr = sb + ((wn + ng * 16 + kn_row) * GHS + k0 + kn_col) * 2;
                ldsm_x4(bfr[ng][0], bfr[ng][1], bfr[ng][2], bfr[ng][3], addr);
            }
            #pragma unroll
            for (int mt = 0; mt < 4; mt++)
                #pragma unroll
                for (int nt = 0; nt < 4; nt++) {
                    uint32_t bf[2] = {bfr[nt >> 1][(nt & 1) * 2],
                                      bfr[nt >> 1][(nt & 1) * 2 + 1]};
                    mma16816h(acc[mt][nt], af[mt], bf);
                }
        }
    }

    #pragma unroll
    for (int mt = 0; mt < 4; mt++) {
        const int row0 = m0 + wm + mt * 16 + g;
        const int row1 = row0 + 8;
        #pragma unroll
        for (int nt = 0; nt < 4; nt++) {
            const int col = n0 + wn + nt * 8 + t * 2;
            const float b0 = bias[col], b1 = bias[col + 1];
            *(__half2*)(C + (size_t)row0 * N + col) =
                __floats2half2_rn(acc[mt][nt][0] + b0, acc[mt][nt][1] + b1);
            *(__half2*)(C + (size_t)row1 * N + col) =
                __floats2half2_rn(acc[mt][nt][2] + b0, acc[mt][nt][3] + b1);
        }
    }
}

__global__ void __launch_bounds__(512, 1) gemm_qkv(
    const __half* Aq, const __half* Ak, const __half* Av,
    const __half* Wq, const __half* Wk, const __half* Wv,
    const float* bq, const float* bk, const float* bv,
    __half* Cq, __half* Ck, __half* Cv)
{
    extern __shared__ __half gsm[];
    const int z = blockIdx.z;
    const __half* A = (z == 0) ? Aq : (z == 1) ? Ak : Av;
    const __half* W = (z == 0) ? Wq : (z == 1) ? Wk : Wv;
    const float*  b = (z == 0) ? bq : (z == 1) ? bk : bv;
    __half*       C = (z == 0) ? Cq : (z == 1) ? Ck : Cv;
    gemm_core(A, W, b, C, MROWS, HDIM, HDIM, gsm,
              blockIdx.y * 256, blockIdx.x * 128);
}

__global__ void __launch_bounds__(512, 1) gemm_o(
    const __half* A, const __half* W, const float* bias, __half* C)
{
    extern __shared__ __half gsm[];
    gemm_core(A, W, bias, C, MROWS, HDIM, HDIM, gsm,
              blockIdx.y * 256, blockIdx.x * 128);
}

// ---------------- FA2-style fp16 flash attention (causal), 128 q-rows --------
#define KS_STR 72
#define A_STAGE (64 * KS_STR)
#define A_SMEM_HALVES (3 * 2 * A_STAGE)

__global__ void __launch_bounds__(256) attn_fa(
    const __half* __restrict__ Qh, const __half* __restrict__ Kh,
    const __half* __restrict__ Vh, __half* __restrict__ O)
{
    extern __shared__ __half asm_[];
    __half* Ks = asm_;
    __half* Vs = asm_ + 3 * A_STAGE;

    const int tid  = threadIdx.x;
    const int w    = tid >> 5;
    const int lane = tid & 31;
    const int g    = lane >> 2;
    const int t    = lane & 3;
    const int wq   = w * 16;

    const int q0 = (gridDim.x - 1 - blockIdx.x) * 128;
    const int h  = blockIdx.y;
    const int b  = blockIdx.z;

    const uint32_t ks_base = (uint32_t)__cvta_generic_to_shared(Ks);
    const uint32_t vs_base = (uint32_t)__cvta_generic_to_shared(Vs);
    const uint32_t stage_b = A_STAGE * 2;

    const __half* Qg = Qh + ((size_t)(b * SEQ + q0)) * HDIM + h * HD;
    #pragma unroll
    for (int j = 0; j < 4; j++) {
        int i = tid + j * 256;
        int r = i >> 3;
        int c8 = (i & 7) * 8;
        cp16(ks_base + (r * KS_STR + c8) * 2, Qg + (size_t)r * HDIM + c8);
    }
    cp_commit();
    cp_wait<0>();
    __syncthreads();

    uint32_t qf[4][4];
    {
        const __half2 sc = __half2half2(__float2half(0.125f * 1.44269504f));
        const int row = wq + (lane & 15);
        const int chi = (lane >> 4) * 8;
        #pragma unroll
        for (int ks = 0; ks < 4; ks++) {
            uint32_t addr = ks_base + (row * KS_STR + ks * 16 + chi) * 2;
            ldsm_x4(qf[ks][0], qf[ks][1], qf[ks][2], qf[ks][3], addr);
            #pragma unroll
            for (int r = 0; r < 4; r++) {
                __half2 v = *(__half2*)&qf[ks][r];
                v = __hmul2(v, sc);
                qf[ks][r] = *(uint32_t*)&v;
            }
        }
    }
    __syncthreads();

    float m0r = -1e30f, m1r = -1e30f, l0r = 0.f, l1r = 0.f;
    float oacc[8][4];
    #pragma unroll
    for (int j = 0; j < 8; j++)
        #pragma unroll
        for (int r = 0; r < 4; r++) oacc[j][r] = 0.f;

    const int kn_row = (lane & 7) + ((lane >> 4) & 1) * 8;
    const int kn_col = ((lane >> 3) & 1) * 8;
    const int vk_row = (lane & 7) + ((lane >> 3) & 1) * 8;
    const int vn_col = (lane >> 4) * 8;

    const int jmax = (q0 + 127) / 64;

    #pragma unroll
    for (int p = 0; p < 2; p++) {
        if (p <= jmax) {
            const uint32_t st = p * stage_b;
            const __half* Kg = Kh + ((size_t)(b * SEQ + p * 64)) * HDIM + h * HD;
            const __half* Vg = Vh + ((size_t)(b * SEQ + p * 64)) * HDIM + h * HD;
            #pragma unroll
            for (int j = 0; j < 2; j++) {
                int i = tid + j * 256;
                int r = i >> 3;
                int c8 = (i & 7) * 8;
                cp16(ks_base + st + (r * KS_STR + c8) * 2, Kg + (size_t)r * HDIM + c8);
                cp16(vs_base + st + (r * KS_STR + c8) * 2, Vg + (size_t)r * HDIM + c8);
            }
        }
        cp_commit();
    }

    for (int jt = 0; jt <= jmax; jt++) {
        const int k0g = jt * 64;

        cp_wait<1>();
        __syncthreads();

        if (jt + 2 <= jmax) {
            const int s = (jt + 2) % 3;
            const uint32_t st = s * stage_b;
            const __half* Kg = Kh + ((size_t)(b * SEQ + (jt + 2) * 64)) * HDIM + h * HD;
            const __half* Vg = Vh + ((size_t)(b * SEQ + (jt + 2) * 64)) * HDIM + h * HD;
            #pragma unroll
            for (int j = 0; j < 2; j++) {
                int i = tid + j * 256;
                int r = i >> 3;
                int c8 = (i & 7) * 8;
                cp16(ks_base + st + (r * KS_STR + c8) * 2, Kg + (size_t)r * HDIM + c8);
                cp16(vs_base + st + (r * KS_STR + c8) * 2, Vg + (size_t)r * HDIM + c8);
            }
        }
        cp_commit();

        const uint32_t sk = ks_base + (jt % 3) * stage_b;
        const uint32_t sv = vs_base + (jt % 3) * stage_b;

        const bool active = (k0g <= q0 + wq + 15);
        if (active) {
            float sacc[8][4];
            #pragma unroll
            for (int j = 0; j < 8; j++)
                #pragma unroll
                for (int r = 0; r < 4; r++) sacc[j][r] = 0.f;

            #pragma unroll
            for (int ks = 0; ks < 4; ks++) {
                #pragma unroll
                for (int ng = 0; ng < 4; ng++) {
                    uint32_t b0, b1, b2, b3;
                    uint32_t addr = sk + ((ng * 16 + kn_row) * KS_STR + ks * 16 + kn_col) * 2;
                    ldsm_x4(b0, b1, b2, b3, addr);
                    uint32_t bf0[2] = {b0, b1}, bf1[2] = {b2, b3};
                    mma16816h(sacc[ng * 2],     qf[ks], bf0);
                    mma16816h(sacc[ng * 2 + 1], qf[ks], bf1);
                }
            }

            if (k0g + 63 > q0 + wq) {
                const int row0 = q0 + wq + g;
                const int row1 = row0 + 8;
                #pragma unroll
                for (int j = 0; j < 8; j++) {
                    const int col = k0g + j * 8 + t * 2;
                    if (col > row0)     sacc[j][0] = -1e30f;
                    if (col + 1 > row0) sacc[j][1] = -1e30f;
                    if (col > row1)     sacc[j][2] = -1e30f;
                    if (col + 1 > row1) sacc[j][3] = -1e30f;
                }
            }

            float tm0 = -1e30f, tm1 = -1e30f;
            #pragma unroll
            for (int j = 0; j < 8; j++) {
                tm0 = fmaxf(tm0, fmaxf(sacc[j][0], sacc[j][1]));
                tm1 = fmaxf(tm1, fmaxf(sacc[j][2], sacc[j][3]));
            }
            tm0 = fmaxf(tm0, __shfl_xor_sync(0xffffffffu, tm0, 1));
            tm0 = fmaxf(tm0, __shfl_xor_sync(0xffffffffu, tm0, 2));
            tm1 = fmaxf(tm1, __shfl_xor_sync(0xffffffffu, tm1, 1));
            tm1 = fmaxf(tm1, __shfl_xor_sync(0xffffffffu, tm1, 2));

            const float mn0 = fmaxf(m0r, tm0);
            const float mn1 = fmaxf(m1r, tm1);
            const float al0 = exp2f(m0r - mn0);
            const float al1 = exp2f(m1r - mn1);
            m0r = mn0; m1r = mn1;

            float rs0 = 0.f, rs1 = 0.f;
            #pragma unroll
            for (int j = 0; j < 8; j++) {
                sacc[j][0] = exp2f(sacc[j][0] - mn0);
                sacc[j][1] = exp2f(sacc[j][1] - mn0);
                sacc[j][2] = exp2f(sacc[j][2] - mn1);
                sacc[j][3] = exp2f(sacc[j][3] - mn1);
                rs0 += sacc[j][0] + sacc[j][1];
                rs1 += sacc[j][2] + sacc[j][3];
            }
            rs0 += __shfl_xor_sync(0xffffffffu, rs0, 1);
            rs0 += __shfl_xor_sync(0xffffffffu, rs0, 2);
            rs1 += __shfl_xor_sync(0xffffffffu, rs1, 1);
            rs1 += __shfl_xor_sync(0xffffffffu, rs1, 2);
            l0r = l0r * al0 + rs0;
            l1r = l1r * al1 + rs1;

            uint32_t pa[4][4];
            #pragma unroll
            for (int ks = 0; ks < 4; ks++) {
                __half2 h0 = __floats2half2_rn(sacc[2*ks][0],   sacc[2*ks][1]);
                __half2 h1 = __floats2half2_rn(sacc[2*ks][2],   sacc[2*ks][3]);
                __half2 h2 = __floats2half2_rn(sacc[2*ks+1][0], sacc[2*ks+1][1]);
                __half2 h3 = __floats2half2_rn(sacc[2*ks+1][2], sacc[2*ks+1][3]);
                pa[ks][0] = *(uint32_t*)&h0; pa[ks][1] = *(uint32_t*)&h1;
                pa[ks][2] = *(uint32_t*)&h2; pa[ks][3] = *(uint32_t*)&h3;
            }

            #pragma unroll
            for (int j = 0; j < 8; j++) {
                oacc[j][0] *= al0; oacc[j][1] *= al0;
                oacc[j][2] *= al1; oacc[j][3] *= al1;
            }
            #pragma unroll
            for (int ks = 0; ks < 4; ks++) {
                #pragma unroll
                for (int ng = 0; ng < 4; ng++) {
                    uint32_t b0, b1, b2, b3;
                    uint32_t addr = sv + ((ks * 16 + vk_row) * KS_STR + ng * 16 + vn_col) * 2;
                    ldsm_x4t(b0, b1, b2, b3, addr);
                    uint32_t bf0[2] = {b0, b1}, bf1[2] = {b2, b3};
                    mma16816h(oacc[ng * 2],     pa[ks], bf0);
                    mma16816h(oacc[ng * 2 + 1], pa[ks], bf1);
                }
            }
        }
    }

    const float il0 = 1.f / l0r;
    const float il1 = 1.f / l1r;
    __half* Og = O + ((size_t)(b * SEQ + q0 + wq)) * HDIM + h * HD;
    #pragma unroll
    for (int j = 0; j < 8; j++) {
        const int col = j * 8 + t * 2;
        *(__half2*)(Og + (size_t)g * HDIM + col) =
            __floats2half2_rn(oacc[j][0] * il0, oacc[j][1] * il0);
        *(__half2*)(Og + (size_t)(g + 8) * HDIM + col) =
            __floats2half2_rn(oacc[j][2] * il1, oacc[j][3] * il1);
    }
}

// ---------------- Residual + LayerNorm: 2 rows / 256-thread block ------------
// Half-block (128 threads) per row; per-row reduce via shuffles + 4-slot smem.
__global__ void __launch_bounds__(256) ln_kernel(
    const float* __restrict__ X, const __half* __restrict__ Y,
    const float* __restrict__ g, const float* __restrict__ be,
    float* __restrict__ out)
{
    const int tid  = threadIdx.x;
    const int half = tid >> 7;            // 0 or 1 -> which row
    const int lt   = tid & 127;           // lane within row-group
    const int row  = blockIdx.x * 2 + half;

    const float* xr = X + (size_t)row * HDIM;
    const __half* yr = Y + (size_t)row * HDIM;
    const int c = lt * 8;                 // 8 elems per thread (128 thr * 8 = 1024)

    float4 xa = *(const float4*)(xr + c);
    float4 xb = *(const float4*)(xr + c + 4);
    __half2 y0h = *(const __half2*)(yr + c);
    __half2 y1h = *(const __half2*)(yr + c + 2);
    __half2 y2h = *(const __half2*)(yr + c + 4);
    __half2 y3h = *(const __half2*)(yr + c + 6);
    float2 y0 = __half22float2(y0h), y1 = __half22float2(y1h);
    float2 y2 = __half22float2(y2h), y3 = __half22float2(y3h);

    float v[8];
    v[0] = xa.x + y0.x; v[1] = xa.y + y0.y; v[2] = xa.z + y1.x; v[3] = xa.w + y1.y;
    v[4] = xb.x + y2.x; v[5] = xb.y + y2.y; v[6] = xb.z + y3.x; v[7] = xb.w + y3.y;

    float s = 0.f, ss = 0.f;
    #pragma unroll
    for (int i = 0; i < 8; i++) { s += v[i]; ss += v[i] * v[i]; }
    #pragma unroll
    for (int off = 16; off > 0; off >>= 1) {
        s  += __shfl_xor_sync(0xffffffffu, s, off);
        ss += __shfl_xor_sync(0xffffffffu, ss, off);
    }

    __shared__ float sbuf[8], ssbuf[8];
    __shared__ float mu_s[2], rstd_s[2];
    if ((tid & 31) == 0) { sbuf[tid >> 5] = s; ssbuf[tid >> 5] = ss; }
    __syncthreads();
    if ((lt & 127) == 0) {                // one thread per row-group
        const int b0 = half * 4;
        float S = sbuf[b0] + sbuf[b0+1] + sbuf[b0+2] + sbuf[b0+3];
        float SS = ssbuf[b0] + ssbuf[b0+1] + ssbuf[b0+2] + ssbuf[b0+3];
        float mu = S * (1.0f / HDIM);
        float var = SS * (1.0f / HDIM) - mu * mu;
        mu_s[half] = mu;
        rstd_s[half] = rsqrtf(var + 1e-5f);
    }
    __syncthreads();
    const float mu = mu_s[half], rs = rstd_s[half];

    float4 ga = *(const float4*)(g + c);
    float4 gb = *(const float4*)(g + c + 4);
    float4 ba = *(const float4*)(be + c);
    float4 bb = *(const float4*)(be + c + 4);
    float4 o0, o1;
    o0.x = (v[0] - mu) * rs * ga.x + ba.x;
    o0.y = (v[1] - mu) * rs * ga.y + ba.y;
    o0.z = (v[2] - mu) * rs * ga.z + ba.z;
    o0.w = (v[3] - mu) * rs * ga.w + ba.w;
    o1.x = (v[4] - mu) * rs * gb.x + bb.x;
    o1.y = (v[5] - mu) * rs * gb.y + bb.y;
    o1.z = (v[6] - mu) * rs * gb.z + bb.z;
    o1.w = (v[7] - mu) * rs * gb.w + bb.w;
    *(float4*)(out + (size_t)row * HDIM + c)     = o0;
    *(float4*)(out + (size_t)row * HDIM + c + 4) = o1;
}

// ---------------- launch -----------------------------------------------------
extern "C" void kernel_launch(void* const* d_in, const int* in_sizes, int n_in,
                              void* d_out, int out_size)
{
    const float* query = (const float*)d_in[0];
    const float* key   = (const float*)d_in[1];
    const float* value = (const float*)d_in[2];
    const float* Wq = (const float*)d_in[4];
    const float* bq = (const float*)d_in[5];
    const float* Wk = (const float*)d_in[6];
    const float* bk = (const float*)d_in[7];
    const float* Wv = (const float*)d_in[8];
    const float* bv = (const float*)d_in[9];
    const float* Wo = (const float*)d_in[10];
    const float* bo = (const float*)d_in[11];
    const float* lg = (const float*)d_in[12];
    const float* lb = (const float*)d_in[13];
    float* out = (float*)d_out;

    __half *dQh, *dKh, *dVh, *dAOh, *dYh, *dqx, *dkx, *dvx, *dWq, *dWk, *dWv, *dWo;
    cudaGetSymbolAddress((void**)&dQh, g_Qh);
    cudaGetSymbolAddress((void**)&dKh, g_Kh);
    cudaGetSymbolAddress((void**)&dVh, g_Vh);
    cudaGetSymbolAddress((void**)&dAOh, g_AOh);
    cudaGetSymbolAddress((void**)&dYh, g_Yh);
    cudaGetSymbolAddress((void**)&dqx, g_qx);
    cudaGetSymbolAddress((void**)&dkx, g_kx);
    cudaGetSymbolAddress((void**)&dvx, g_vx);
    cudaGetSymbolAddress((void**)&dWq, g_Wqh);
    cudaGetSymbolAddress((void**)&dWk, g_Wkh);
    cudaGetSymbolAddress((void**)&dWv, g_Wvh);
    cudaGetSymbolAddress((void**)&dWo, g_Woh);

    const int nbig = MROWS * HDIM;
    const int nsmall = HDIM * HDIM;
    dim3 gCvt(nbig / (256 * 4), 7);
    cvt7<<<gCvt, 256>>>(query, key, value, Wq, Wk, Wv, Wo,
                        dqx, dkx, dvx, dWq, dWk, dWv, dWo, nbig, nsmall);

    cudaFuncSetAttribute(gemm_qkv, cudaFuncAttributeMaxDynamicSharedMemorySize, G_SMEM_BYTES);
    cudaFuncSetAttribute(gemm_o,   cudaFuncAttributeMaxDynamicSharedMemorySize, G_SMEM_BYTES);
    const int attn_smem = A_SMEM_HALVES * 2;
    cudaFuncSetAttribute(attn_fa, cudaFuncAttributeMaxDynamicSharedMemorySize, attn_smem);

    dim3 gQKV(HDIM / 128, MROWS / 256, 3);           // (8, 16, 3)
    gemm_qkv<<<gQKV, 512, G_SMEM_BYTES>>>(dqx, dkx, dvx, dWq, dWk, dWv,
                                          bq, bk, bv, dQh, dKh, dVh);

    attn_fa<<<dim3(SEQ / 128, NHEAD, BATCH), 256, attn_smem>>>(dQh, dKh, dVh, dAOh);

    dim3 gO(HDIM / 128, MROWS / 256);                // (8, 16)
    gemm_o<<<gO, 512, G_SMEM_BYTES>>>(dAOh, dWo, bo, dYh);

    ln_kernel<<<MROWS / 2, 256>>>(query, dYh, lg, lb, out);
}

// round 15
// speedup vs baseline: 1.0390x; 1.0017x over previous
#include <cuda_runtime.h>
#include <cuda_fp16.h>
#include <cstdint>

#define BATCH 2
#define SEQ   2048
#define HDIM  1024
#define NHEAD 16
#define HD    64
#define MROWS (BATCH * SEQ)   // 4096

// ---------------- scratch (device globals: allocation-free) ------------------
__device__ __half g_Qh[MROWS * HDIM];
__device__ __half g_Kh[MROWS * HDIM];
__device__ __half g_Vh[MROWS * HDIM];
__device__ __half g_AOh[MROWS * HDIM];
__device__ __half g_Yh[MROWS * HDIM];
__device__ __half g_qx[MROWS * HDIM];
__device__ __half g_kx[MROWS * HDIM];
__device__ __half g_vx[MROWS * HDIM];
__device__ __half g_Wqh[HDIM * HDIM];
__device__ __half g_Wkh[HDIM * HDIM];
__device__ __half g_Wvh[HDIM * HDIM];
__device__ __half g_Woh[HDIM * HDIM];

// ---------------- helpers ----------------------------------------------------
__device__ __forceinline__ void mma16816h(float* c, const uint32_t* a, const uint32_t* b) {
    asm volatile(
        "mma.sync.aligned.m16n8k16.row.col.f32.f16.f16.f32 "
        "{%0,%1,%2,%3},{%4,%5,%6,%7},{%8,%9},{%0,%1,%2,%3};"
        : "+f"(c[0]), "+f"(c[1]), "+f"(c[2]), "+f"(c[3])
        : "r"(a[0]), "r"(a[1]), "r"(a[2]), "r"(a[3]), "r"(b[0]), "r"(b[1]));
}

__device__ __forceinline__ void ldsm_x4(uint32_t& r0, uint32_t& r1, uint32_t& r2,
                                        uint32_t& r3, uint32_t addr) {
    asm volatile("ldmatrix.sync.aligned.m8n8.x4.shared.b16 {%0,%1,%2,%3}, [%4];"
                 : "=r"(r0), "=r"(r1), "=r"(r2), "=r"(r3) : "r"(addr));
}
__device__ __forceinline__ void ldsm_x4t(uint32_t& r0, uint32_t& r1, uint32_t& r2,
                                         uint32_t& r3, uint32_t addr) {
    asm volatile("ldmatrix.sync.aligned.m8n8.x4.trans.shared.b16 {%0,%1,%2,%3}, [%4];"
                 : "=r"(r0), "=r"(r1), "=r"(r2), "=r"(r3) : "r"(addr));
}

__device__ __forceinline__ void cp16(uint32_t dst, const void* src) {
    asm volatile("cp.async.cg.shared.global [%0], [%1], 16;" :: "r"(dst), "l"(src));
}
__device__ __forceinline__ void cp_commit() {
    asm volatile("cp.async.commit_group;");
}
template <int N>
__device__ __forceinline__ void cp_wait() {
    asm volatile("cp.async.wait_group %0;" :: "n"(N));
}

// ---------------- fp32 -> fp16 batched convert --------------------------------
__global__ void __launch_bounds__(256) cvt7(
    const float* s0, const float* s1, const float* s2, const float* s3,
    const float* s4, const float* s5, const float* s6,
    __half* d0, __half* d1, __half* d2, __half* d3,
    __half* d4, __half* d5, __half* d6,
    int nbig, int nsmall)
{
    const float* s;
    __half* d;
    int n;
    switch (blockIdx.y) {
        case 0: s = s0; d = d0; n = nbig; break;
        case 1: s = s1; d = d1; n = nbig; break;
        case 2: s = s2; d = d2; n = nbig; break;
        case 3: s = s3; d = d3; n = nsmall; break;
        case 4: s = s4; d = d4; n = nsmall; break;
        case 5: s = s5; d = d5; n = nsmall; break;
        default: s = s6; d = d6; n = nsmall; break;
    }
    int idx = (blockIdx.x * 256 + threadIdx.x) * 4;
    if (idx < n) {
        float4 v = *(const float4*)(s + idx);
        *(__half2*)(d + idx)     = __floats2half2_rn(v.x, v.y);
        *(__half2*)(d + idx + 2) = __floats2half2_rn(v.z, v.w);
    }
}

// ---------------- fp16 GEMM: C = A[M,K] @ W[N,K]^T + bias (fp16 out) ---------
// 256x128 CTA tile, BK=32, 3-stage cp.async ring, 16 warps (4x4), warp 64x32.
#define GHS 40
#define A_ST (256 * GHS)
#define B_ST (128 * GHS)
#define PAIR_ST (A_ST + B_ST)
#define G_SMEM_BYTES (3 * PAIR_ST * 2)

__device__ __forceinline__ void gemm_core(
    const __half* __restrict__ A, const __half* __restrict__ W,
    const float* __restrict__ bias, __half* __restrict__ C,
    int M, int N, int K, __half* smem, int m0, int n0)
{
    const int tid  = threadIdx.x;
    const int w    = tid >> 5;
    const int lane = tid & 31;
    const int g    = lane >> 2;
    const int t    = lane & 3;
    const int wm   = (w >> 2) * 64;
    const int wn   = (w & 3) * 32;

    const uint32_t s_base = (uint32_t)__cvta_generic_to_shared(smem);

    const int a_row  = lane & 15;
    const int a_chi  = (lane >> 4) * 8;
    const int kn_row = (lane & 7) + ((lane >> 4) & 1) * 8;
    const int kn_col = ((lane >> 3) & 1) * 8;

    float acc[4][4][4];
    #pragma unroll
    for (int i = 0; i < 4; i++)
        #pragma unroll
        for (int j = 0; j < 4; j++)
            #pragma unroll
            for (int r = 0; r < 4; r++) acc[i][j][r] = 0.f;

    const int niter = K / 32;

    auto load_stage = [&](int stage, int kb) {
        const uint32_t sa = s_base + (uint32_t)stage * (PAIR_ST * 2);
        const uint32_t sb = sa + A_ST * 2;
        #pragma unroll
        for (int j = 0; j < 3; j++) {
            int cid = tid + j * 512;
            if (cid < 1024) {
                int r  = cid >> 2;
                int ch = (cid & 3) * 8;
                cp16(sa + (r * GHS + ch) * 2,
                     A + (size_t)(m0 + r) * K + kb * 32 + ch);
            } else {
                int c2 = cid - 1024;
                int r  = c2 >> 2;
                int ch = (c2 & 3) * 8;
                cp16(sb + (r * GHS + ch) * 2,
                     W + (size_t)(n0 + r) * K + kb * 32 + ch);
            }
        }
    };

    load_stage(0, 0); cp_commit();
    load_stage(1, 1); cp_commit();

    for (int kb = 0; kb < niter; kb++) {
        cp_wait<1>();
        __syncthreads();

        if (kb + 2 < niter) load_stage((kb + 2) % 3, kb + 2);
        cp_commit();

        const int cs = kb % 3;
        const uint32_t sa = s_base + (uint32_t)cs * (PAIR_ST * 2);
        const uint32_t sb = sa + A_ST * 2;

        #pragma unroll
        for (int ks = 0; ks < 2; ks++) {
            const int k0 = ks * 16;
            uint32_t af[4][4];
            #pragma unroll
            for (int mt = 0; mt < 4; mt++) {
                uint32_t addr = sa + ((wm + mt * 16 + a_row) * GHS + k0 + a_chi) * 2;
                ldsm_x4(af[mt][0], af[mt][1], af[mt][2], af[mt][3], addr);
            }
            uint32_t bfr[2][4];
            #pragma unroll
            for (int ng = 0; ng < 2; ng++) {
                uint32_t addr = sb + ((wn + ng * 16 + kn_row) * GHS + k0 + kn_col) * 2;
                ldsm_x4(bfr[ng][0], bfr[ng][1], bfr[ng][2], bfr[ng][3], addr);
            }
            #pragma unroll
            for (int mt = 0; mt < 4; mt++)
                #pragma unroll
                for (int nt = 0; nt < 4; nt++) {
                    uint32_t bf[2] = {bfr[nt >> 1][(nt & 1) * 2],
                                      bfr[nt >> 1][(nt & 1) * 2 + 1]};
                    mma16816h(acc[mt][nt], af[mt], bf);
                }
        }
    }

    #pragma unroll
    for (int mt = 0; mt < 4; mt++) {
        const int row0 = m0 + wm + mt * 16 + g;
        const int row1 = row0 + 8;
        #pragma unroll
        for (int nt = 0; nt < 4; nt++) {
            const int col = n0 + wn + nt * 8 + t * 2;
            const float b0 = bias[col], b1 = bias[col + 1];
            *(__half2*)(C + (size_t)row0 * N + col) =
                __floats2half2_rn(acc[mt][nt][0] + b0, acc[mt][nt][1] + b1);
            *(__half2*)(C + (size_t)row1 * N + col) =
                __floats2half2_rn(acc[mt][nt][2] + b0, acc[mt][nt][3] + b1);
        }
    }
}

__global__ void __launch_bounds__(512, 1) gemm_qkv(
    const __half* Aq, const __half* Ak, const __half* Av,
    const __half* Wq, const __half* Wk, const __half* Wv,
    const float* bq, const float* bk, const float* bv,
    __half* Cq, __half* Ck, __half* Cv)
{
    extern __shared__ __half gsm[];
    const int z = blockIdx.z;
    const __half* A = (z == 0) ? Aq : (z == 1) ? Ak : Av;
    const __half* W = (z == 0) ? Wq : (z == 1) ? Wk : Wv;
    const float*  b = (z == 0) ? bq : (z == 1) ? bk : bv;
    __half*       C = (z == 0) ? Cq : (z == 1) ? Ck : Cv;
    gemm_core(A, W, b, C, MROWS, HDIM, HDIM, gsm,
              blockIdx.y * 256, blockIdx.x * 128);
}

__global__ void __launch_bounds__(512, 1) gemm_o(
    const __half* A, const __half* W, const float* bias, __half* C)
{
    extern __shared__ __half gsm[];
    gemm_core(A, W, bias, C, MROWS, HDIM, HDIM, gsm,
              blockIdx.y * 256, blockIdx.x * 128);
}

// ---------------- FA2-style fp16 flash attention (causal) --------------------
// 128 q-rows/block (8 warps x 16 rows), KV-tile 128, 3-stage cp.async ring.
#define KS_STR 72
#define TR 128                               // kv rows per tile
#define A_STAGE (TR * KS_STR)                // 9216 halves per stage
#define A_SMEM_BYTES (3 * 2 * A_STAGE * 2)   // 110592 B

__global__ void __launch_bounds__(256) attn_fa(
    const __half* __restrict__ Qh, const __half* __restrict__ Kh,
    const __half* __restrict__ Vh, __half* __restrict__ O)
{
    extern __shared__ __half asm_[];
    __half* Ks = asm_;
    __half* Vs = asm_ + 3 * A_STAGE;

    const int tid  = threadIdx.x;
    const int w    = tid >> 5;
    const int lane = tid & 31;
    const int g    = lane >> 2;
    const int t    = lane & 3;
    const int wq   = w * 16;

    const int q0 = (gridDim.x - 1 - blockIdx.x) * 128;
    const int h  = blockIdx.y;
    const int b  = blockIdx.z;

    const uint32_t ks_base = (uint32_t)__cvta_generic_to_shared(Ks);
    const uint32_t vs_base = (uint32_t)__cvta_generic_to_shared(Vs);
    const uint32_t stage_b = A_STAGE * 2;

    // ---- stage Q tile [128][64] into Ks stage 0 ------------------------------
    const __half* Qg = Qh + ((size_t)(b * SEQ + q0)) * HDIM + h * HD;
    #pragma unroll
    for (int j = 0; j < 4; j++) {
        int i = tid + j * 256;
        int r = i >> 3;
        int c8 = (i & 7) * 8;
        cp16(ks_base + (r * KS_STR + c8) * 2, Qg + (size_t)r * HDIM + c8);
    }
    cp_commit();
    cp_wait<0>();
    __syncthreads();

    uint32_t qf[4][4];
    {
        const __half2 sc = __half2half2(__float2half(0.125f * 1.44269504f));
        const int row = wq + (lane & 15);
        const int chi = (lane >> 4) * 8;
        #pragma unroll
        for (int ks = 0; ks < 4; ks++) {
            uint32_t addr = ks_base + (row * KS_STR + ks * 16 + chi) * 2;
            ldsm_x4(qf[ks][0], qf[ks][1], qf[ks][2], qf[ks][3], addr);
            #pragma unroll
            for (int r = 0; r < 4; r++) {
                __half2 v = *(__half2*)&qf[ks][r];
                v = __hmul2(v, sc);
                qf[ks][r] = *(uint32_t*)&v;
            }
        }
    }
    __syncthreads();

    float m0r = -1e30f, m1r = -1e30f, l0r = 0.f, l1r = 0.f;
    float oacc[8][4];
    #pragma unroll
    for (int j = 0; j < 8; j++)
        #pragma unroll
        for (int r = 0; r < 4; r++) oacc[j][r] = 0.f;

    const int kn_row = (lane & 7) + ((lane >> 4) & 1) * 8;
    const int kn_col = ((lane >> 3) & 1) * 8;
    const int vk_row = (lane & 7) + ((lane >> 3) & 1) * 8;
    const int vn_col = (lane >> 4) * 8;

    const int jmax = q0 / TR;   // tiles of 128 kv rows, covers cols <= q0+127

    // prologue: tiles 0,1 (1024 K + 1024 V chunks each; 4 K + 4 V per thread)
    #pragma unroll
    for (int p = 0; p < 2; p++) {
        if (p <= jmax) {
            const uint32_t st = p * stage_b;
            const __half* Kg = Kh + ((size_t)(b * SEQ + p * TR)) * HDIM + h * HD;
            const __half* Vg = Vh + ((size_t)(b * SEQ + p * TR)) * HDIM + h * HD;
            #pragma unroll
            for (int j = 0; j < 4; j++) {
                int i = tid + j * 256;
                int r = i >> 3;
                int c8 = (i & 7) * 8;
                cp16(ks_base + st + (r * KS_STR + c8) * 2, Kg + (size_t)r * HDIM + c8);
                cp16(vs_base + st + (r * KS_STR + c8) * 2, Vg + (size_t)r * HDIM + c8);
            }
        }
        cp_commit();
    }

    for (int jt = 0; jt <= jmax; jt++) {
        const int k0g = jt * TR;

        cp_wait<1>();
        __syncthreads();

        if (jt + 2 <= jmax) {
            const int s = (jt + 2) % 3;
            const uint32_t st = s * stage_b;
            const __half* Kg = Kh + ((size_t)(b * SEQ + (jt + 2) * TR)) * HDIM + h * HD;
            const __half* Vg = Vh + ((size_t)(b * SEQ + (jt + 2) * TR)) * HDIM + h * HD;
            #pragma unroll
            for (int j = 0; j < 4; j++) {
                int i = tid + j * 256;
                int r = i >> 3;
                int c8 = (i & 7) * 8;
                cp16(ks_base + st + (r * KS_STR + c8) * 2, Kg + (size_t)r * HDIM + c8);
                cp16(vs_base + st + (r * KS_STR + c8) * 2, Vg + (size_t)r * HDIM + c8);
            }
        }
        cp_commit();

        const uint32_t sk = ks_base + (jt % 3) * stage_b;
        const uint32_t sv = vs_base + (jt % 3) * stage_b;

        const bool active = (k0g <= q0 + wq + 15);
        if (active) {
            // ---- S = Q @ K^T over 128 kv cols: sacc[16][4] -------------------
            float sacc[16][4];
            #pragma unroll
            for (int j = 0; j < 16; j++)
                #pragma unroll
                for (int r = 0; r < 4; r++) sacc[j][r] = 0.f;

            #pragma unroll
            for (int ks = 0; ks < 4; ks++) {
                #pragma unroll
                for (int ng = 0; ng < 8; ng++) {
                    uint32_t b0, b1, b2, b3;
                    uint32_t addr = sk + ((ng * 16 + kn_row) * KS_STR + ks * 16 + kn_col) * 2;
                    ldsm_x4(b0, b1, b2, b3, addr);
                    uint32_t bf0[2] = {b0, b1}, bf1[2] = {b2, b3};
                    mma16816h(sacc[ng * 2],     qf[ks], bf0);
                    mma16816h(sacc[ng * 2 + 1], qf[ks], bf1);
                }
            }

            if (k0g + TR - 1 > q0 + wq) {    // diagonal region
                const int row0 = q0 + wq + g;
                const int row1 = row0 + 8;
                #pragma unroll
                for (int j = 0; j < 16; j++) {
                    const int col = k0g + j * 8 + t * 2;
                    if (col > row0)     sacc[j][0] = -1e30f;
                    if (col + 1 > row0) sacc[j][1] = -1e30f;
                    if (col > row1)     sacc[j][2] = -1e30f;
                    if (col + 1 > row1) sacc[j][3] = -1e30f;
                }
            }

            float tm0 = -1e30f, tm1 = -1e30f;
            #pragma unroll
            for (int j = 0; j < 16; j++) {
                tm0 = fmaxf(tm0, fmaxf(sacc[j][0], sacc[j][1]));
                tm1 = fmaxf(tm1, fmaxf(sacc[j][2], sacc[j][3]));
            }
            tm0 = fmaxf(tm0, __shfl_xor_sync(0xffffffffu, tm0, 1));
            tm0 = fmaxf(tm0, __shfl_xor_sync(0xffffffffu, tm0, 2));
            tm1 = fmaxf(tm1, __shfl_xor_sync(0xffffffffu, tm1, 1));
            tm1 = fmaxf(tm1, __shfl_xor_sync(0xffffffffu, tm1, 2));

            const float mn0 = fmaxf(m0r, tm0);
            const float mn1 = fmaxf(m1r, tm1);
            const float al0 = exp2f(m0r - mn0);
            const float al1 = exp2f(m1r - mn1);
            m0r = mn0; m1r = mn1;

            float rs0 = 0.f, rs1 = 0.f;
            #pragma unroll
            for (int j = 0; j < 16; j++) {
                sacc[j][0] = exp2f(sacc[j][0] - mn0);
                sacc[j][1] = exp2f(sacc[j][1] - mn0);
                sacc[j][2] = exp2f(sacc[j][2] - mn1);
                sacc[j][3] = exp2f(sacc[j][3] - mn1);
                rs0 += sacc[j][0] + sacc[j][1];
                rs1 += sacc[j][2] + sacc[j][3];
            }
            rs0 += __shfl_xor_sync(0xffffffffu, rs0, 1);
            rs0 += __shfl_xor_sync(0xffffffffu, rs0, 2);
            rs1 += __shfl_xor_sync(0xffffffffu, rs1, 1);
            rs1 += __shfl_xor_sync(0xffffffffu, rs1, 2);
            l0r = l0r * al0 + rs0;
            l1r = l1r * al1 + rs1;

            // P fragments: 8 k16-steps over the 128 kv dim
            uint32_t pa[8][4];
            #pragma unroll
            for (int ks = 0; ks < 8; ks++) {
                __half2 h0 = __floats2half2_rn(sacc[2*ks][0],   sacc[2*ks][1]);
                __half2 h1 = __floats2half2_rn(sacc[2*ks][2],   sacc[2*ks][3]);
                __half2 h2 = __floats2half2_rn(sacc[2*ks+1][0], sacc[2*ks+1][1]);
                __half2 h3 = __floats2half2_rn(sacc[2*ks+1][2], sacc[2*ks+1][3]);
                pa[ks][0] = *(uint32_t*)&h0; pa[ks][1] = *(uint32_t*)&h1;
                pa[ks][2] = *(uint32_t*)&h2; pa[ks][3] = *(uint32_t*)&h3;
            }

            #pragma unroll
            for (int j = 0; j < 8; j++) {
                oacc[j][0] *= al0; oacc[j][1] *= al0;
                oacc[j][2] *= al1; oacc[j][3] *= al1;
            }
            #pragma unroll
            for (int ks = 0; ks < 8; ks++) {
                #pragma unroll
                for (int ng = 0; ng < 4; ng++) {
                    uint32_t b0, b1, b2, b3;
                    uint32_t addr = sv + ((ks * 16 + vk_row) * KS_STR + ng * 16 + vn_col) * 2;
                    ldsm_x4t(b0, b1, b2, b3, addr);
                    uint32_t bf0[2] = {b0, b1}, bf1[2] = {b2, b3};
                    mma16816h(oacc[ng * 2],     pa[ks], bf0);
                    mma16816h(oacc[ng * 2 + 1], pa[ks], bf1);
                }
            }
        }
    }

    const float il0 = 1.f / l0r;
    const float il1 = 1.f / l1r;
    __half* Og = O + ((size_t)(b * SEQ + q0 + wq)) * HDIM + h * HD;
    #pragma unroll
    for (int j = 0; j < 8; j++) {
        const int col = j * 8 + t * 2;
        *(__half2*)(Og + (size_t)g * HDIM + col) =
            __floats2half2_rn(oacc[j][0] * il0, oacc[j][1] * il0);
        *(__half2*)(Og + (size_t)(g + 8) * HDIM + col) =
            __floats2half2_rn(oacc[j][2] * il1, oacc[j][3] * il1);
    }
}

// ---------------- Residual + LayerNorm: 2 rows / 256-thread block ------------
__global__ void __launch_bounds__(256) ln_kernel(
    const float* __restrict__ X, const __half* __restrict__ Y,
    const float* __restrict__ g, const float* __restrict__ be,
    float* __restrict__ out)
{
    const int tid  = threadIdx.x;
    const int half = tid >> 7;
    const int lt   = tid & 127;
    const int row  = blockIdx.x * 2 + half;

    const float* xr = X + (size_t)row * HDIM;
    const __half* yr = Y + (size_t)row * HDIM;
    const int c = lt * 8;

    float4 xa = *(const float4*)(xr + c);
    float4 xb = *(const float4*)(xr + c + 4);
    __half2 y0h = *(const __half2*)(yr + c);
    __half2 y1h = *(const __half2*)(yr + c + 2);
    __half2 y2h = *(const __half2*)(yr + c + 4);
    __half2 y3h = *(const __half2*)(yr + c + 6);
    float2 y0 = __half22float2(y0h), y1 = __half22float2(y1h);
    float2 y2 = __half22float2(y2h), y3 = __half22float2(y3h);

    float v[8];
    v[0] = xa.x + y0.x; v[1] = xa.y + y0.y; v[2] = xa.z + y1.x; v[3] = xa.w + y1.y;
    v[4] = xb.x + y2.x; v[5] = xb.y + y2.y; v[6] = xb.z + y3.x; v[7] = xb.w + y3.y;

    float s = 0.f, ss = 0.f;
    #pragma unroll
    for (int i = 0; i < 8; i++) { s += v[i]; ss += v[i] * v[i]; }
    #pragma unroll
    for (int off = 16; off > 0; off >>= 1) {
        s  += __shfl_xor_sync(0xffffffffu, s, off);
        ss += __shfl_xor_sync(0xffffffffu, ss, off);
    }

    __shared__ float sbuf[8], ssbuf[8];
    __shared__ float mu_s[2], rstd_s[2];
    if ((tid & 31) == 0) { sbuf[tid >> 5] = s; ssbuf[tid >> 5] = ss; }
    __syncthreads();
    if ((lt & 127) == 0) {
        const int b0 = half * 4;
        float S = sbuf[b0] + sbuf[b0+1] + sbuf[b0+2] + sbuf[b0+3];
        float SS = ssbuf[b0] + ssbuf[b0+1] + ssbuf[b0+2] + ssbuf[b0+3];
        float mu = S * (1.0f / HDIM);
        float var = SS * (1.0f / HDIM) - mu * mu;
        mu_s[half] = mu;
        rstd_s[half] = rsqrtf(var + 1e-5f);
    }
    __syncthreads();
    const float mu = mu_s[half], rs = rstd_s[half];

    float4 ga = *(const float4*)(g + c);
    float4 gb = *(const float4*)(g + c + 4);
    float4 ba = *(const float4*)(be + c);
    float4 bb = *(const float4*)(be + c + 4);
    float4 o0, o1;
    o0.x = (v[0] - mu) * rs * ga.x + ba.x;
    o0.y = (v[1] - mu) * rs * ga.y + ba.y;
    o0.z = (v[2] - mu) * rs * ga.z + ba.z;
    o0.w = (v[3] - mu) * rs * ga.w + ba.w;
    o1.x = (v[4] - mu) * rs * gb.x + bb.x;
    o1.y = (v[5] - mu) * rs * gb.y + bb.y;
    o1.z = (v[6] - mu) * rs * gb.z + bb.z;
    o1.w = (v[7] - mu) * rs * gb.w + bb.w;
    *(float4*)(out + (size_t)row * HDIM + c)     = o0;
    *(float4*)(out + (size_t)row * HDIM + c + 4) = o1;
}

// ---------------- launch -----------------------------------------------------
extern "C" void kernel_launch(void* const* d_in, const int* in_sizes, int n_in,
                              void* d_out, int out_size)
{
    const float* query = (const float*)d_in[0];
    const float* key   = (const float*)d_in[1];
    const float* value = (const float*)d_in[2];
    const float* Wq = (const float*)d_in[4];
    const float* bq = (const float*)d_in[5];
    const float* Wk = (const float*)d_in[6];
    const float* bk = (const float*)d_in[7];
    const float* Wv = (const float*)d_in[8];
    const float* bv = (const float*)d_in[9];
    const float* Wo = (const float*)d_in[10];
    const float* bo = (const float*)d_in[11];
    const float* lg = (const float*)d_in[12];
    const float* lb = (const float*)d_in[13];
    float* out = (float*)d_out;

    __half *dQh, *dKh, *dVh, *dAOh, *dYh, *dqx, *dkx, *dvx, *dWq, *dWk, *dWv, *dWo;
    cudaGetSymbolAddress((void**)&dQh, g_Qh);
    cudaGetSymbolAddress((void**)&dKh, g_Kh);
    cudaGetSymbolAddress((void**)&dVh, g_Vh);
    cudaGetSymbolAddress((void**)&dAOh, g_AOh);
    cudaGetSymbolAddress((void**)&dYh, g_Yh);
    cudaGetSymbolAddress((void**)&dqx, g_qx);
    cudaGetSymbolAddress((void**)&dkx, g_kx);
    cudaGetSymbolAddress((void**)&dvx, g_vx);
    cudaGetSymbolAddress((void**)&dWq, g_Wqh);
    cudaGetSymbolAddress((void**)&dWk, g_Wkh);
    cudaGetSymbolAddress((void**)&dWv, g_Wvh);
    cudaGetSymbolAddress((void**)&dWo, g_Woh);

    const int nbig = MROWS * HDIM;
    const int nsmall = HDIM * HDIM;
    dim3 gCvt(nbig / (256 * 4), 7);
    cvt7<<<gCvt, 256>>>(query, key, value, Wq, Wk, Wv, Wo,
                        dqx, dkx, dvx, dWq, dWk, dWv, dWo, nbig, nsmall);

    cudaFuncSetAttribute(gemm_qkv, cudaFuncAttributeMaxDynamicSharedMemorySize, G_SMEM_BYTES);
    cudaFuncSetAttribute(gemm_o,   cudaFuncAttributeMaxDynamicSharedMemorySize, G_SMEM_BYTES);
    cudaFuncSetAttribute(attn_fa, cudaFuncAttributeMaxDynamicSharedMemorySize, A_SMEM_BYTES);

    dim3 gQKV(HDIM / 128, MROWS / 256, 3);           // (8, 16, 3)
    gemm_qkv<<<gQKV, 512, G_SMEM_BYTES>>>(dqx, dkx, dvx, dWq, dWk, dWv,
                                          bq, bk, bv, dQh, dKh, dVh);

    attn_fa<<<dim3(SEQ / 128, NHEAD, BATCH), 256, A_SMEM_BYTES>>>(dQh, dKh, dVh, dAOh);

    dim3 gO(HDIM / 128, MROWS / 256);                // (8, 16)
    gemm_o<<<gO, 512, G_SMEM_BYTES>>>(dAOh, dWo, bo, dYh);

    ln_kernel<<<MROWS / 2, 256>>>(query, dYh, lg, lb, out);
}